// round 13
// baseline (speedup 1.0000x reference)
#include <cuda_runtime.h>
#include <math.h>

typedef unsigned long long ull;

// Problem constants (fixed by reference setup_inputs)
#define B_  8
#define L_  128
#define H_  768
#define P_  16
#define OUTD 102
#define EPSF 1e-8f
#define NEGINF (-1e30f)
#define TT 16           // token tile for attention kernel (128 blocks, 1/SM)
#define ATT_THR 384     // 384 threads = 768 h / 2 packed
#define ATT_W   12      // warps per att block

// ---------------- scratch (static device memory; no allocation) ----------------
__device__ float g_c[2][B_*L_*H_];      // masked contexts
__device__ float g_n[2][B_*L_];         // plain L2 norms
__device__ float g_nw[2][B_*L_*P_];     // w_mp-weighted norms
__device__ float g_Scos[B_*L_*L_];      // cosine channel (for k_att)
__device__ float g_attS[2][B_*L_*H_];   // att softmax (att_mean)
__device__ float g_attM[2][B_*L_*H_];   // att maxes
__device__ int   g_len[2][B_];

// ---------------- packed fp32x2 helpers ----------------
#define FMA2(d,a,b)    asm("fma.rn.f32x2 %0, %1, %2, %0;" : "+l"(d) : "l"(a), "l"(b))
#define MUL2(d,a,b)    asm("mul.rn.f32x2 %0, %1, %2;" : "=l"(d) : "l"(a), "l"(b))
#define PACK2(d,x)     asm("mov.b64 %0, {%1, %2};" : "=l"(d) : "f"(x), "f"(x))
#define UNPK2(lo,hi,v) asm("mov.b64 {%0, %1}, %2;" : "=f"(lo), "=f"(hi) : "l"(v))

__device__ __forceinline__ ull lds64(unsigned int addr) {
    ull v; asm volatile("ld.shared.b64 %0, [%1];" : "=l"(v) : "r"(addr)); return v;
}
__device__ __forceinline__ void sts64(unsigned int addr, ull v) {
    asm volatile("st.shared.b64 [%0], %1;" :: "r"(addr), "l"(v) : "memory");
}
__device__ __forceinline__ ull ldg64(const float* p) {
    ull v; asm volatile("ld.global.nc.b64 %0, [%1];" : "=l"(v) : "l"(p)); return v;
}

// ---------------- lengths ----------------
__global__ void k_len(const float* __restrict__ m1, const float* __restrict__ m2) {
    int t = threadIdx.x;
    if (t < 16) {
        int s = t >> 3, b = t & 7;
        const float* mk = s ? m2 : m1;
        float acc = 0.f;
        for (int j = 0; j < L_; j++) acc += mk[b*L_ + j];
        g_len[s][b] = (int)(acc + 0.5f);
    }
}

// ---------------- masked context + norms ----------------
__global__ __launch_bounds__(256) void k_prep(
    const float* __restrict__ ctx1, const float* __restrict__ m1,
    const float* __restrict__ ctx2, const float* __restrict__ m2,
    const float* __restrict__ w_mp)
{
    int i = blockIdx.x, b = blockIdx.y, s = blockIdx.z;
    const float* ctx = s ? ctx2 : ctx1;
    const float* mk  = s ? m2   : m1;
    __shared__ float cs[H_];
    float m = mk[b*L_ + i];
    int tid = threadIdx.x;
    float* cdst = g_c[s] + (size_t)(b*L_ + i) * H_;
    const float* csrc = ctx + (size_t)(b*L_ + i) * H_;
    for (int h = tid; h < H_; h += 256) {
        float v = csrc[h] * m;
        cs[h] = v;
        cdst[h] = v;
    }
    __syncthreads();
    int w = tid >> 5, lane = tid & 31;
    for (int t = w; t < P_ + 1; t += 8) {
        float acc = 0.f;
        #pragma unroll
        for (int k = 0; k < H_/32; k++) {
            int h = lane + 32*k;
            float c = cs[h];
            float x = (t < P_) ? w_mp[t*H_ + h] * c : c;
            acc = fmaf(x, x, acc);
        }
        #pragma unroll
        for (int o = 16; o; o >>= 1) acc += __shfl_xor_sync(0xffffffffu, acc, o);
        if (lane == 0) {
            if (t == P_) g_n[s][b*L_ + i] = sqrtf(acc);
            else         g_nw[s][(b*L_ + i)*P_ + t] = sqrtf(acc);
        }
    }
}

// ---------------- 16-channel WEIGHTED pairwise GEMM + masked reductions ----------------
// grid (P_, B): one 128x128 tile per block (channel p), stats -> out cols 36..67
__global__ __launch_bounds__(256) void k_gemm(
    const float* __restrict__ w_mp,
    const float* __restrict__ m1, const float* __restrict__ m2,
    float* __restrict__ out)
{
    int p = blockIdx.x, b = blockIdx.y;
    const float* A  = g_c[0] + (size_t)b * L_ * H_;
    const float* Bm = g_c[1] + (size_t)b * L_ * H_;
    __shared__ __align__(16) float As[16][128];
    __shared__ __align__(16) float Bs[16][128];
    __shared__ float mA[L_], mB[L_];
    __shared__ float red[16][132];
    int tid = threadIdx.x;
    if (tid < 128) mA[tid] = m1[b*L_ + tid];
    else           mB[tid-128] = m2[b*L_ + tid - 128];

    int lr = tid & 127, lk = (tid >> 7) << 3;
    int tr = tid >> 4,  tc = tid & 15;
    const float* wp = w_mp + p * H_;

    ull acc[8][4];
    #pragma unroll
    for (int r = 0; r < 8; r++)
        #pragma unroll
        for (int q = 0; q < 4; q++) acc[r][q] = 0ull;

    unsigned int bs_b = (unsigned int)__cvta_generic_to_shared(&Bs[0][0]);

    float4 pa0, pa1, pb0, pb1;
    {
        const float* Ap = A  + (size_t)lr * H_ + lk;
        const float* Bp = Bm + (size_t)lr * H_ + lk;
        pa0 = *(const float4*)(Ap);     pa1 = *(const float4*)(Ap + 4);
        pb0 = *(const float4*)(Bp);     pb1 = *(const float4*)(Bp + 4);
        float4 w0 = *(const float4*)(wp + lk);
        float4 w1 = *(const float4*)(wp + lk + 4);
        pa0.x*=w0.x; pa0.y*=w0.y; pa0.z*=w0.z; pa0.w*=w0.w;
        pa1.x*=w1.x; pa1.y*=w1.y; pa1.z*=w1.z; pa1.w*=w1.w;
        pb0.x*=w0.x; pb0.y*=w0.y; pb0.z*=w0.z; pb0.w*=w0.w;
        pb1.x*=w1.x; pb1.y*=w1.y; pb1.z*=w1.z; pb1.w*=w1.w;
    }

    for (int c = 0; c < H_/16; c++) {
        As[lk+0][lr]=pa0.x; As[lk+1][lr]=pa0.y; As[lk+2][lr]=pa0.z; As[lk+3][lr]=pa0.w;
        As[lk+4][lr]=pa1.x; As[lk+5][lr]=pa1.y; As[lk+6][lr]=pa1.z; As[lk+7][lr]=pa1.w;
        Bs[lk+0][lr]=pb0.x; Bs[lk+1][lr]=pb0.y; Bs[lk+2][lr]=pb0.z; Bs[lk+3][lr]=pb0.w;
        Bs[lk+4][lr]=pb1.x; Bs[lk+5][lr]=pb1.y; Bs[lk+6][lr]=pb1.z; Bs[lk+7][lr]=pb1.w;
        __syncthreads();
        if (c + 1 < H_/16) {
            int k0 = (c + 1) * 16;
            const float* Ap = A  + (size_t)lr * H_ + k0 + lk;
            const float* Bp = Bm + (size_t)lr * H_ + k0 + lk;
            pa0 = *(const float4*)(Ap);     pa1 = *(const float4*)(Ap + 4);
            pb0 = *(const float4*)(Bp);     pb1 = *(const float4*)(Bp + 4);
            float4 w0 = *(const float4*)(wp + k0 + lk);
            float4 w1 = *(const float4*)(wp + k0 + lk + 4);
            pa0.x*=w0.x; pa0.y*=w0.y; pa0.z*=w0.z; pa0.w*=w0.w;
            pa1.x*=w1.x; pa1.y*=w1.y; pa1.z*=w1.z; pa1.w*=w1.w;
            pb0.x*=w0.x; pb0.y*=w0.y; pb0.z*=w0.z; pb0.w*=w0.w;
            pb1.x*=w1.x; pb1.y*=w1.y; pb1.z*=w1.z; pb1.w*=w1.w;
        }
        #pragma unroll
        for (int k = 0; k < 16; k++) {
            float4 ra0 = *(const float4*)&As[k][tr << 3];
            float4 ra1 = *(const float4*)&As[k][(tr << 3) + 4];
            unsigned int bb = bs_b + (unsigned int)((((k << 7) + (tc << 1))) << 2);
            ull b0 = lds64(bb);
            ull b1 = lds64(bb + 32*4);
            ull b2 = lds64(bb + 64*4);
            ull b3 = lds64(bb + 96*4);
            float av[8] = {ra0.x, ra0.y, ra0.z, ra0.w, ra1.x, ra1.y, ra1.z, ra1.w};
            #pragma unroll
            for (int r = 0; r < 8; r++) {
                ull aa; PACK2(aa, av[r]);
                FMA2(acc[r][0], aa, b0);
                FMA2(acc[r][1], aa, b1);
                FMA2(acc[r][2], aa, b2);
                FMA2(acc[r][3], aa, b3);
            }
        }
        __syncthreads();
    }

    float val[8][8];
    #pragma unroll
    for (int r = 0; r < 8; r++)
        #pragma unroll
        for (int q = 0; q < 4; q++)
            UNPK2(val[r][2*q], val[r][2*q+1], acc[r][q]);

    {
        float dl[8], dr[8];
        #pragma unroll
        for (int r = 0; r < 8; r++) dl[r] = g_nw[0][(b*L_ + (tr*8 + r))*P_ + p];
        #pragma unroll
        for (int q = 0; q < 4; q++) {
            dr[2*q]   = g_nw[1][(b*L_ + tc*2 + 32*q    )*P_ + p];
            dr[2*q+1] = g_nw[1][(b*L_ + tc*2 + 32*q + 1)*P_ + p];
        }
        #pragma unroll
        for (int r = 0; r < 8; r++)
            #pragma unroll
            for (int cc = 0; cc < 8; cc++)
                val[r][cc] /= fmaxf(dl[r] * dr[cc], EPSF);   // clip PRODUCT (ref)
    }

    float rm[8], cmk[8];
    #pragma unroll
    for (int r = 0; r < 8; r++) rm[r] = mA[tr*8 + r];
    #pragma unroll
    for (int q = 0; q < 4; q++) {
        cmk[2*q]   = mB[tc*2 + 32*q];
        cmk[2*q+1] = mB[tc*2 + 32*q + 1];
    }
    float cnt2 = fmaxf((float)g_len[1][b], EPSF);
    float cnt1 = fmaxf((float)g_len[0][b], EPSF);

    // row reductions (over j, mask_2)
    #pragma unroll
    for (int r = 0; r < 8; r++) {
        float mx = NEGINF, sm = 0.f;
        #pragma unroll
        for (int cc = 0; cc < 8; cc++)
            if (cmk[cc] != 0.f) { mx = fmaxf(mx, val[r][cc]); sm += val[r][cc]; }
        #pragma unroll
        for (int o = 8; o; o >>= 1) {
            mx = fmaxf(mx, __shfl_xor_sync(0xffffffffu, mx, o));
            sm += __shfl_xor_sync(0xffffffffu, sm, o);
        }
        if (tc == 0) {
            int i = tr*8 + r;
            float* o_ = out + ((size_t)(b*2 + 0)*L_ + i) * OUTD;
            o_[36 + p] = mx; o_[52 + p] = sm / cnt2;
        }
    }

    // col reductions (over i, mask_1)
    float cmx[8], csm[8];
    #pragma unroll
    for (int cc = 0; cc < 8; cc++) { cmx[cc] = NEGINF; csm[cc] = 0.f; }
    #pragma unroll
    for (int r = 0; r < 8; r++)
        if (rm[r] != 0.f)
            #pragma unroll
            for (int cc = 0; cc < 8; cc++) {
                cmx[cc] = fmaxf(cmx[cc], val[r][cc]);
                csm[cc] += val[r][cc];
            }
    #pragma unroll
    for (int q = 0; q < 4; q++) {
        red[tr][tc*2 + 32*q]     = cmx[2*q];
        red[tr][tc*2 + 32*q + 1] = cmx[2*q+1];
    }
    __syncthreads();
    float fmx = NEGINF;
    if (tid < 128) {
        fmx = red[0][tid];
        #pragma unroll
        for (int t = 1; t < 16; t++) fmx = fmaxf(fmx, red[t][tid]);
    }
    __syncthreads();
    #pragma unroll
    for (int q = 0; q < 4; q++) {
        red[tr][tc*2 + 32*q]     = csm[2*q];
        red[tr][tc*2 + 32*q + 1] = csm[2*q+1];
    }
    __syncthreads();
    if (tid < 128) {
        float fsm = 0.f;
        #pragma unroll
        for (int t = 0; t < 16; t++) fsm += red[t][tid];
        float* o_ = out + ((size_t)(b*2 + 1)*L_ + tid) * OUTD;
        o_[36 + p] = fmx; o_[52 + p] = fsm / cnt1;
    }
}

// ---------------- cosine channel GEMM (8-row stripes, grid (16,B) = 128 blocks) ----------------
// Per thread: rows {2tr, 2tr+1}, col pair 2tc. Register-prefetched chunks.
__global__ __launch_bounds__(256) void k_gcos() {
    int b = blockIdx.y;
    int r0 = blockIdx.x * 8;
    const float* A  = g_c[0] + (size_t)(b*L_ + r0) * H_;
    const float* Bm = g_c[1] + (size_t)b * L_ * H_;
    __shared__ __align__(16) ull As2[16][8];        // pre-duplicated {a,a}
    __shared__ __align__(16) float Bs[16][128];
    int tid = threadIdx.x;
    int lr = tid & 127, lk = (tid >> 7) << 3;       // B loader
    int ar = tid >> 2, ak = (tid & 3) << 2;         // A loader (tid<32)
    int tr = tid >> 6, tc = tid & 63;               // compute

    ull acc0 = 0ull, acc1 = 0ull;
    unsigned int bs_b = (unsigned int)__cvta_generic_to_shared(&Bs[0][0]);
    unsigned int as_b = (unsigned int)__cvta_generic_to_shared(&As2[0][0]);

    float4 pb0, pb1, pa;
    pb0 = *(const float4*)(Bm + (size_t)lr * H_ + lk);
    pb1 = *(const float4*)(Bm + (size_t)lr * H_ + lk + 4);
    if (tid < 32) pa = *(const float4*)(A + (size_t)ar * H_ + ak);

    for (int c = 0; c < H_/16; c++) {
        Bs[lk+0][lr]=pb0.x; Bs[lk+1][lr]=pb0.y; Bs[lk+2][lr]=pb0.z; Bs[lk+3][lr]=pb0.w;
        Bs[lk+4][lr]=pb1.x; Bs[lk+5][lr]=pb1.y; Bs[lk+6][lr]=pb1.z; Bs[lk+7][lr]=pb1.w;
        if (tid < 32) {
            ull w;
            PACK2(w, pa.x); As2[ak+0][ar] = w;
            PACK2(w, pa.y); As2[ak+1][ar] = w;
            PACK2(w, pa.z); As2[ak+2][ar] = w;
            PACK2(w, pa.w); As2[ak+3][ar] = w;
        }
        __syncthreads();
        if (c + 1 < H_/16) {
            int k0 = (c + 1) * 16;
            pb0 = *(const float4*)(Bm + (size_t)lr * H_ + k0 + lk);
            pb1 = *(const float4*)(Bm + (size_t)lr * H_ + k0 + lk + 4);
            if (tid < 32) pa = *(const float4*)(A + (size_t)ar * H_ + k0 + ak);
        }
        #pragma unroll
        for (int k = 0; k < 16; k++) {
            ull aa0 = lds64(as_b + (unsigned int)(((k << 3) + 2*tr) << 3));
            ull aa1 = lds64(as_b + (unsigned int)(((k << 3) + 2*tr + 1) << 3));
            ull bb  = lds64(bs_b + (unsigned int)(((k << 7) + 2*tc) << 2));
            FMA2(acc0, aa0, bb);
            FMA2(acc1, aa1, bb);
        }
        __syncthreads();
    }

    float dl0 = fmaxf(g_n[0][b*L_ + r0 + 2*tr],     EPSF);
    float dl1 = fmaxf(g_n[0][b*L_ + r0 + 2*tr + 1], EPSF);
    float drx = fmaxf(g_n[1][b*L_ + 2*tc],          EPSF);
    float dry = fmaxf(g_n[1][b*L_ + 2*tc + 1],      EPSF);
    float l0, h0, l1, h1;
    UNPK2(l0, h0, acc0);
    UNPK2(l1, h1, acc1);
    float* d0 = g_Scos + ((size_t)(b*L_ + r0 + 2*tr    )) * L_ + 2*tc;
    float* d1 = g_Scos + ((size_t)(b*L_ + r0 + 2*tr + 1)) * L_ + 2*tc;
    *(float2*)d0 = make_float2(l0/(dl0*drx), h0/(dl0*dry));
    *(float2*)d1 = make_float2(l1/(dl1*drx), h1/(dl1*dry));
}

// ---------------- attention sums/maxes + cos stats + fused softmax ----------------
#define ATT_BODY(CC, U) do {                                              \
    unsigned int _ub = cw_b + (unsigned int)((U) << 3);                   \
    _Pragma("unroll")                                                     \
    for (int tt = 0; tt < TT; tt++) {                                     \
        ull ww = lds64(_ub + (unsigned int)(tt * (L_*8)));                \
        ull pp; MUL2(pp, ww, (CC));                                       \
        FMA2(sm2[tt], ww, (CC));                                          \
        float pl, ph; UNPK2(pl, ph, pp);                                  \
        mxl[tt] = fmaxf(mxl[tt], pl);                                     \
        mxh[tt] = fmaxf(mxh[tt], ph);                                     \
    }                                                                     \
} while (0)

__global__ __launch_bounds__(ATT_THR) void k_att(
    const float* __restrict__ m1, const float* __restrict__ m2,
    float* __restrict__ out)
{
    int tb = blockIdx.x, b = blockIdx.y, s = blockIdx.z;
    int other = 1 - s;
    int lenO = g_len[other][b];           // always >= 64
    const float* C = g_c[other] + (size_t)b * L_ * H_;
    const float* Scos = g_Scos + (size_t)b * L_ * L_;
    const float* mkS = s ? m2 : m1;
    const float* mkO = s ? m1 : m2;       // mask over the reduced axis u
    __shared__ __align__(16) ull cw2[TT][L_];       // {w,w} duplicated pairs
    __shared__ float rmx[TT][ATT_W], rsm[TT][ATT_W];
    int tid = threadIdx.x;
    for (int idx = tid; idx < TT*L_; idx += ATT_THR) {
        int tt = idx >> 7, u = idx & (L_-1);
        int t = tb*TT + tt;
        float w = (s == 0) ? Scos[(size_t)t * L_ + u] : Scos[(size_t)u * L_ + t];
        ull ww; PACK2(ww, w);
        cw2[tt][u] = ww;
    }
    __syncthreads();

    int w = tid >> 5, lane = tid & 31;

    // cosine-channel masked max/mean over u  ->  out cols 0,1
    for (int tt = w; tt < TT; tt += ATT_W) {
        int t = tb*TT + tt;
        float mx = NEGINF, sm = 0.f;
        #pragma unroll
        for (int k4 = 0; k4 < 4; k4++) {
            int u = lane + (k4 << 5);
            float v = ((const float*)&cw2[tt][u])[0];
            if (mkO[b*L_ + u] != 0.f) { mx = fmaxf(mx, v); sm += v; }
        }
        #pragma unroll
        for (int o = 16; o; o >>= 1) {
            mx = fmaxf(mx, __shfl_xor_sync(0xffffffffu, mx, o));
            sm += __shfl_xor_sync(0xffffffffu, sm, o);
        }
        if (lane == 0) {
            float* o_ = out + ((size_t)(b*2 + s)*L_ + t) * OUTD;
            o_[0] = mx;
            o_[1] = sm / fmaxf((float)lenO, EPSF);
        }
    }

    unsigned int cw_b = (unsigned int)__cvta_generic_to_shared(&cw2[0][0]);
    ull sm2[TT];
    float mxl[TT], mxh[TT];
    #pragma unroll
    for (int tt = 0; tt < TT; tt++) { sm2[tt] = 0ull; mxl[tt] = NEGINF; mxh[tt] = NEGINF; }

    const float* Cp = C + 2*tid;
    // depth-4 prefetch ring (rows beyond lenO are zero-masked but valid; clamp to L_-1)
    ull c0 = ldg64(Cp);
    ull c1 = ldg64(Cp + H_);
    ull c2 = ldg64(Cp + 2*H_);
    ull c3 = ldg64(Cp + 3*H_);
    int u = 0;
    for (; u + 4 <= lenO; u += 4) {
        int n0 = u+4 < L_ ? u+4 : L_-1;
        int n1 = u+5 < L_ ? u+5 : L_-1;
        int n2 = u+6 < L_ ? u+6 : L_-1;
        int n3 = u+7 < L_ ? u+7 : L_-1;
        ATT_BODY(c0, u);     c0 = ldg64(Cp + (size_t)n0 * H_);
        ATT_BODY(c1, u+1);   c1 = ldg64(Cp + (size_t)n1 * H_);
        ATT_BODY(c2, u+2);   c2 = ldg64(Cp + (size_t)n2 * H_);
        ATT_BODY(c3, u+3);   c3 = ldg64(Cp + (size_t)n3 * H_);
    }
    if (u < lenO) { ATT_BODY(c0, u); u++; }
    if (u < lenO) { ATT_BODY(c1, u); u++; }
    if (u < lenO) { ATT_BODY(c2, u); u++; }

    // store maxes
    #pragma unroll
    for (int tt = 0; tt < TT; tt++) {
        int t = tb*TT + tt;
        size_t base = ((size_t)(b*L_ + t)) * H_;
        *(float2*)(&g_attM[s][base + 2*tid]) = make_float2(mxl[tt], mxh[tt]);
    }

    // fused softmax: stage per-warp partial maxes for all tokens, one sync
    float s0[TT], s1[TT];
    #pragma unroll
    for (int tt = 0; tt < TT; tt++) {
        UNPK2(s0[tt], s1[tt], sm2[tt]);
        float lm = fmaxf(s0[tt], s1[tt]);
        #pragma unroll
        for (int o = 16; o; o >>= 1) lm = fmaxf(lm, __shfl_xor_sync(0xffffffffu, lm, o));
        if (lane == 0) rmx[tt][w] = lm;
    }
    __syncthreads();
    float bm[TT];
    #pragma unroll
    for (int tt = 0; tt < TT; tt++) {
        float m = rmx[tt][0];
        #pragma unroll
        for (int i = 1; i < ATT_W; i++) m = fmaxf(m, rmx[tt][i]);
        bm[tt] = m;
    }
    float e0[TT], e1[TT];
    #pragma unroll
    for (int tt = 0; tt < TT; tt++) {
        e0[tt] = expf(s0[tt] - bm[tt]);
        e1[tt] = expf(s1[tt] - bm[tt]);
        float ls = e0[tt] + e1[tt];
        #pragma unroll
        for (int o = 16; o; o >>= 1) ls += __shfl_xor_sync(0xffffffffu, ls, o);
        if (lane == 0) rsm[tt][w] = ls;
    }
    __syncthreads();
    #pragma unroll
    for (int tt = 0; tt < TT; tt++) {
        int t = tb*TT + tt;
        size_t base = ((size_t)(b*L_ + t)) * H_;
        float m = mkS[b*L_ + t];
        if (m == 0.f) {
            *(float2*)(&g_attS[s][base + 2*tid]) = make_float2(1.f/(float)H_, 1.f/(float)H_);
            continue;
        }
        float bs = 0.f;
        #pragma unroll
        for (int i = 0; i < ATT_W; i++) bs += rsm[tt][i];
        float inv = 1.f / bs;
        *(float2*)(&g_attS[s][base + 2*tid]) = make_float2(e0[tt]*inv, e1[tt]*inv);
    }
}

// ---------------- per-token weighted cosines (packed f32x2) ----------------
__global__ __launch_bounds__(256) void k_final(
    const float* __restrict__ wff, const float* __restrict__ wfb,
    const float* __restrict__ watt, const float* __restrict__ wmatt,
    float* __restrict__ out)
{
    int t = blockIdx.x, b = blockIdx.y, s = blockIdx.z;
    int other = 1 - s;
    __shared__ __align__(16) float sa[H_];
    __shared__ __align__(16) float sv[4][H_];
    int tid = threadIdx.x;
    const float* a = g_c[s] + ((size_t)(b*L_ + t)) * H_;
    int lenO = g_len[other][b];
    int lp = lenO > 0 ? lenO - 1 : 0;
    const float* v_ff  = g_c[other] + ((size_t)(b*L_ + lp)) * H_;
    const float* v_bf  = g_c[other] + ((size_t)(b*L_)) * H_;
    const float* v_am  = g_attS[s] + ((size_t)(b*L_ + t)) * H_;
    const float* v_amx = g_attM[s] + ((size_t)(b*L_ + t)) * H_;
    for (int h = tid; h < H_; h += 256) {
        sa[h] = a[h];
        sv[0][h] = v_ff[h];
        sv[1][h] = v_bf[h];
        sv[2][h] = v_am[h];
        sv[3][h] = v_amx[h];
    }
    __syncthreads();

    unsigned int sa_b = (unsigned int)__cvta_generic_to_shared(sa);
    unsigned int sv_b = (unsigned int)__cvta_generic_to_shared(&sv[0][0]);
    int w = tid >> 5, lane = tid & 31;
    float* o_ = out + ((size_t)(b*2 + s)*L_ + t) * OUTD;
    for (int task = w; task < 68; task += 8) {
        int q = task / 17;
        int tt = task - q * 17;
        const float* W = (q == 0) ? wff : (q == 1) ? wfb : (q == 2) ? watt : wmatt;
        int base = (q == 0) ? 2 : (q == 1) ? 19 : (q == 2) ? 68 : 85;
        const float* Wr = W + tt * H_;
        unsigned int svq = sv_b + (unsigned int)(q * H_ * 4);
        ull sav = 0ull, saa = 0ull, svv = 0ull;
        if (tt < P_) {
            #pragma unroll
            for (int k = 0; k < 12; k++) {
                int h2 = (lane + (k << 5)) << 1;
                ull a2 = lds64(sa_b + (unsigned int)(h2 << 2));
                ull v2 = lds64(svq  + (unsigned int)(h2 << 2));
                ull w2 = ldg64(Wr + h2);
                MUL2(a2, a2, w2);
                MUL2(v2, v2, w2);
                FMA2(sav, a2, v2);
                FMA2(saa, a2, a2);
                FMA2(svv, v2, v2);
            }
        } else {
            #pragma unroll
            for (int k = 0; k < 12; k++) {
                int h2 = (lane + (k << 5)) << 1;
                ull a2 = lds64(sa_b + (unsigned int)(h2 << 2));
                ull v2 = lds64(svq  + (unsigned int)(h2 << 2));
                FMA2(sav, a2, v2);
                FMA2(saa, a2, a2);
                FMA2(svv, v2, v2);
            }
        }
        float lo, hi, fsav, fsaa, fsvv;
        UNPK2(lo, hi, sav); fsav = lo + hi;
        UNPK2(lo, hi, saa); fsaa = lo + hi;
        UNPK2(lo, hi, svv); fsvv = lo + hi;
        #pragma unroll
        for (int o = 16; o; o >>= 1) {
            fsav += __shfl_xor_sync(0xffffffffu, fsav, o);
            fsaa += __shfl_xor_sync(0xffffffffu, fsaa, o);
            fsvv += __shfl_xor_sync(0xffffffffu, fsvv, o);
        }
        if (lane == 0) {
            float na = fmaxf(sqrtf(fsaa), EPSF);
            float nv = fmaxf(sqrtf(fsvv), EPSF);
            int col = (tt == P_) ? base : (base + 1 + tt);
            o_[col] = fsav / (na * nv);
        }
    }
}

// ---------------- launch (fork weighted GEMM onto a side stream) ----------------
extern "C" void kernel_launch(void* const* d_in, const int* in_sizes, int n_in,
                              void* d_out, int out_size) {
    const float* c1    = (const float*)d_in[0];
    const float* m1    = (const float*)d_in[1];
    const float* c2    = (const float*)d_in[2];
    const float* m2    = (const float*)d_in[3];
    const float* wff   = (const float*)d_in[4];
    const float* wfb   = (const float*)d_in[5];
    const float* wmp   = (const float*)d_in[6];
    const float* watt  = (const float*)d_in[7];
    const float* wmatt = (const float*)d_in[8];
    float* out = (float*)d_out;
    (void)in_sizes; (void)n_in; (void)out_size;

    static cudaStream_t sB = nullptr;
    static cudaEvent_t evF = nullptr, evB = nullptr;
    if (!sB) {
        cudaStreamCreateWithFlags(&sB, cudaStreamNonBlocking);
        cudaEventCreateWithFlags(&evF, cudaEventDisableTiming);
        cudaEventCreateWithFlags(&evB, cudaEventDisableTiming);
    }

    k_len  <<<1, 64>>>(m1, m2);
    k_prep <<<dim3(L_, B_, 2), 256>>>(c1, m1, c2, m2, wmp);

    // fork: weighted GEMM on side stream, cosine chain on main stream
    cudaEventRecord(evF, 0);
    cudaStreamWaitEvent(sB, evF, 0);
    k_gemm <<<dim3(P_, B_), 256, 0, sB>>>(wmp, m1, m2, out);
    cudaEventRecord(evB, sB);

    k_gcos  <<<dim3(16, B_), 256>>>();
    k_att   <<<dim3(L_/TT, B_, 2), ATT_THR>>>(m1, m2, out);
    k_final <<<dim3(L_, B_, 2), 256>>>(wff, wfb, watt, wmatt, out);

    // join
    cudaStreamWaitEvent(0, evB, 0);
}

// round 14
// speedup vs baseline: 1.0869x; 1.0869x over previous
#include <cuda_runtime.h>
#include <math.h>

typedef unsigned long long ull;

// Problem constants (fixed by reference setup_inputs)
#define B_  8
#define L_  128
#define H_  768
#define P_  16
#define OUTD 102
#define EPSF 1e-8f
#define NEGINF (-1e30f)
#define TT 16           // token tile for attention kernel (128 blocks, 1/SM)
#define ATT_THR 384     // 384 threads = 768 h / 2 packed
#define ATT_W   12      // warps per att block

// ---------------- scratch (static device memory; no allocation) ----------------
__device__ float g_c[2][B_*L_*H_];      // masked contexts
__device__ float g_n[2][B_*L_];         // plain L2 norms
__device__ float g_nw[2][B_*L_*P_];     // w_mp-weighted norms
__device__ float g_Scos[B_*L_*L_];      // cosine channel (for k_att)
__device__ float g_attS[2][B_*L_*H_];   // att softmax (att_mean)
__device__ float g_attM[2][B_*L_*H_];   // att maxes
__device__ int   g_len[2][B_];

// ---------------- packed fp32x2 helpers ----------------
#define FMA2(d,a,b)    asm("fma.rn.f32x2 %0, %1, %2, %0;" : "+l"(d) : "l"(a), "l"(b))
#define MUL2(d,a,b)    asm("mul.rn.f32x2 %0, %1, %2;" : "=l"(d) : "l"(a), "l"(b))
#define PACK2(d,x)     asm("mov.b64 %0, {%1, %2};" : "=l"(d) : "f"(x), "f"(x))
#define UNPK2(lo,hi,v) asm("mov.b64 {%0, %1}, %2;" : "=f"(lo), "=f"(hi) : "l"(v))

__device__ __forceinline__ ull lds64(unsigned int addr) {
    ull v; asm volatile("ld.shared.b64 %0, [%1];" : "=l"(v) : "r"(addr)); return v;
}
__device__ __forceinline__ void sts64(unsigned int addr, ull v) {
    asm volatile("st.shared.b64 [%0], %1;" :: "r"(addr), "l"(v) : "memory");
}
__device__ __forceinline__ ull ldg64(const float* p) {
    ull v; asm volatile("ld.global.nc.b64 %0, [%1];" : "=l"(v) : "l"(p)); return v;
}

// ---------------- lengths ----------------
__global__ void k_len(const float* __restrict__ m1, const float* __restrict__ m2) {
    int t = threadIdx.x;
    if (t < 16) {
        int s = t >> 3, b = t & 7;
        const float* mk = s ? m2 : m1;
        float acc = 0.f;
        for (int j = 0; j < L_; j++) acc += mk[b*L_ + j];
        g_len[s][b] = (int)(acc + 0.5f);
    }
}

// ---------------- masked context + norms ----------------
__global__ __launch_bounds__(256) void k_prep(
    const float* __restrict__ ctx1, const float* __restrict__ m1,
    const float* __restrict__ ctx2, const float* __restrict__ m2,
    const float* __restrict__ w_mp)
{
    int i = blockIdx.x, b = blockIdx.y, s = blockIdx.z;
    const float* ctx = s ? ctx2 : ctx1;
    const float* mk  = s ? m2   : m1;
    __shared__ float cs[H_];
    float m = mk[b*L_ + i];
    int tid = threadIdx.x;
    float* cdst = g_c[s] + (size_t)(b*L_ + i) * H_;
    const float* csrc = ctx + (size_t)(b*L_ + i) * H_;
    for (int h = tid; h < H_; h += 256) {
        float v = csrc[h] * m;
        cs[h] = v;
        cdst[h] = v;
    }
    __syncthreads();
    int w = tid >> 5, lane = tid & 31;
    for (int t = w; t < P_ + 1; t += 8) {
        float acc = 0.f;
        #pragma unroll
        for (int k = 0; k < H_/32; k++) {
            int h = lane + 32*k;
            float c = cs[h];
            float x = (t < P_) ? w_mp[t*H_ + h] * c : c;
            acc = fmaf(x, x, acc);
        }
        #pragma unroll
        for (int o = 16; o; o >>= 1) acc += __shfl_xor_sync(0xffffffffu, acc, o);
        if (lane == 0) {
            if (t == P_) g_n[s][b*L_ + i] = sqrtf(acc);
            else         g_nw[s][(b*L_ + i)*P_ + t] = sqrtf(acc);
        }
    }
}

// ---------------- 16-channel WEIGHTED pairwise GEMM + masked reductions ----------------
// grid (P_, B): one 128x128 tile per block (channel p), stats -> out cols 36..67
__global__ __launch_bounds__(256) void k_gemm(
    const float* __restrict__ w_mp,
    const float* __restrict__ m1, const float* __restrict__ m2,
    float* __restrict__ out)
{
    int p = blockIdx.x, b = blockIdx.y;
    const float* A  = g_c[0] + (size_t)b * L_ * H_;
    const float* Bm = g_c[1] + (size_t)b * L_ * H_;
    __shared__ __align__(16) float As[16][128];
    __shared__ __align__(16) float Bs[16][128];
    __shared__ float mA[L_], mB[L_];
    __shared__ float red[16][132];
    int tid = threadIdx.x;
    if (tid < 128) mA[tid] = m1[b*L_ + tid];
    else           mB[tid-128] = m2[b*L_ + tid - 128];

    int lr = tid & 127, lk = (tid >> 7) << 3;
    int tr = tid >> 4,  tc = tid & 15;
    const float* wp = w_mp + p * H_;

    ull acc[8][4];
    #pragma unroll
    for (int r = 0; r < 8; r++)
        #pragma unroll
        for (int q = 0; q < 4; q++) acc[r][q] = 0ull;

    unsigned int bs_b = (unsigned int)__cvta_generic_to_shared(&Bs[0][0]);

    float4 pa0, pa1, pb0, pb1;
    {
        const float* Ap = A  + (size_t)lr * H_ + lk;
        const float* Bp = Bm + (size_t)lr * H_ + lk;
        pa0 = *(const float4*)(Ap);     pa1 = *(const float4*)(Ap + 4);
        pb0 = *(const float4*)(Bp);     pb1 = *(const float4*)(Bp + 4);
        float4 w0 = *(const float4*)(wp + lk);
        float4 w1 = *(const float4*)(wp + lk + 4);
        pa0.x*=w0.x; pa0.y*=w0.y; pa0.z*=w0.z; pa0.w*=w0.w;
        pa1.x*=w1.x; pa1.y*=w1.y; pa1.z*=w1.z; pa1.w*=w1.w;
        pb0.x*=w0.x; pb0.y*=w0.y; pb0.z*=w0.z; pb0.w*=w0.w;
        pb1.x*=w1.x; pb1.y*=w1.y; pb1.z*=w1.z; pb1.w*=w1.w;
    }

    for (int c = 0; c < H_/16; c++) {
        As[lk+0][lr]=pa0.x; As[lk+1][lr]=pa0.y; As[lk+2][lr]=pa0.z; As[lk+3][lr]=pa0.w;
        As[lk+4][lr]=pa1.x; As[lk+5][lr]=pa1.y; As[lk+6][lr]=pa1.z; As[lk+7][lr]=pa1.w;
        Bs[lk+0][lr]=pb0.x; Bs[lk+1][lr]=pb0.y; Bs[lk+2][lr]=pb0.z; Bs[lk+3][lr]=pb0.w;
        Bs[lk+4][lr]=pb1.x; Bs[lk+5][lr]=pb1.y; Bs[lk+6][lr]=pb1.z; Bs[lk+7][lr]=pb1.w;
        __syncthreads();
        if (c + 1 < H_/16) {
            int k0 = (c + 1) * 16;
            const float* Ap = A  + (size_t)lr * H_ + k0 + lk;
            const float* Bp = Bm + (size_t)lr * H_ + k0 + lk;
            pa0 = *(const float4*)(Ap);     pa1 = *(const float4*)(Ap + 4);
            pb0 = *(const float4*)(Bp);     pb1 = *(const float4*)(Bp + 4);
            float4 w0 = *(const float4*)(wp + k0 + lk);
            float4 w1 = *(const float4*)(wp + k0 + lk + 4);
            pa0.x*=w0.x; pa0.y*=w0.y; pa0.z*=w0.z; pa0.w*=w0.w;
            pa1.x*=w1.x; pa1.y*=w1.y; pa1.z*=w1.z; pa1.w*=w1.w;
            pb0.x*=w0.x; pb0.y*=w0.y; pb0.z*=w0.z; pb0.w*=w0.w;
            pb1.x*=w1.x; pb1.y*=w1.y; pb1.z*=w1.z; pb1.w*=w1.w;
        }
        #pragma unroll
        for (int k = 0; k < 16; k++) {
            float4 ra0 = *(const float4*)&As[k][tr << 3];
            float4 ra1 = *(const float4*)&As[k][(tr << 3) + 4];
            unsigned int bb = bs_b + (unsigned int)((((k << 7) + (tc << 1))) << 2);
            ull b0 = lds64(bb);
            ull b1 = lds64(bb + 32*4);
            ull b2 = lds64(bb + 64*4);
            ull b3 = lds64(bb + 96*4);
            float av[8] = {ra0.x, ra0.y, ra0.z, ra0.w, ra1.x, ra1.y, ra1.z, ra1.w};
            #pragma unroll
            for (int r = 0; r < 8; r++) {
                ull aa; PACK2(aa, av[r]);
                FMA2(acc[r][0], aa, b0);
                FMA2(acc[r][1], aa, b1);
                FMA2(acc[r][2], aa, b2);
                FMA2(acc[r][3], aa, b3);
            }
        }
        __syncthreads();
    }

    float val[8][8];
    #pragma unroll
    for (int r = 0; r < 8; r++)
        #pragma unroll
        for (int q = 0; q < 4; q++)
            UNPK2(val[r][2*q], val[r][2*q+1], acc[r][q]);

    {
        float dl[8], dr[8];
        #pragma unroll
        for (int r = 0; r < 8; r++) dl[r] = g_nw[0][(b*L_ + (tr*8 + r))*P_ + p];
        #pragma unroll
        for (int q = 0; q < 4; q++) {
            dr[2*q]   = g_nw[1][(b*L_ + tc*2 + 32*q    )*P_ + p];
            dr[2*q+1] = g_nw[1][(b*L_ + tc*2 + 32*q + 1)*P_ + p];
        }
        #pragma unroll
        for (int r = 0; r < 8; r++)
            #pragma unroll
            for (int cc = 0; cc < 8; cc++)
                val[r][cc] /= fmaxf(dl[r] * dr[cc], EPSF);   // clip PRODUCT (ref)
    }

    float rm[8], cmk[8];
    #pragma unroll
    for (int r = 0; r < 8; r++) rm[r] = mA[tr*8 + r];
    #pragma unroll
    for (int q = 0; q < 4; q++) {
        cmk[2*q]   = mB[tc*2 + 32*q];
        cmk[2*q+1] = mB[tc*2 + 32*q + 1];
    }
    float cnt2 = fmaxf((float)g_len[1][b], EPSF);
    float cnt1 = fmaxf((float)g_len[0][b], EPSF);

    // row reductions (over j, mask_2)
    #pragma unroll
    for (int r = 0; r < 8; r++) {
        float mx = NEGINF, sm = 0.f;
        #pragma unroll
        for (int cc = 0; cc < 8; cc++)
            if (cmk[cc] != 0.f) { mx = fmaxf(mx, val[r][cc]); sm += val[r][cc]; }
        #pragma unroll
        for (int o = 8; o; o >>= 1) {
            mx = fmaxf(mx, __shfl_xor_sync(0xffffffffu, mx, o));
            sm += __shfl_xor_sync(0xffffffffu, sm, o);
        }
        if (tc == 0) {
            int i = tr*8 + r;
            float* o_ = out + ((size_t)(b*2 + 0)*L_ + i) * OUTD;
            o_[36 + p] = mx; o_[52 + p] = sm / cnt2;
        }
    }

    // col reductions (over i, mask_1)
    float cmx[8], csm[8];
    #pragma unroll
    for (int cc = 0; cc < 8; cc++) { cmx[cc] = NEGINF; csm[cc] = 0.f; }
    #pragma unroll
    for (int r = 0; r < 8; r++)
        if (rm[r] != 0.f)
            #pragma unroll
            for (int cc = 0; cc < 8; cc++) {
                cmx[cc] = fmaxf(cmx[cc], val[r][cc]);
                csm[cc] += val[r][cc];
            }
    #pragma unroll
    for (int q = 0; q < 4; q++) {
        red[tr][tc*2 + 32*q]     = cmx[2*q];
        red[tr][tc*2 + 32*q + 1] = cmx[2*q+1];
    }
    __syncthreads();
    float fmx = NEGINF;
    if (tid < 128) {
        fmx = red[0][tid];
        #pragma unroll
        for (int t = 1; t < 16; t++) fmx = fmaxf(fmx, red[t][tid]);
    }
    __syncthreads();
    #pragma unroll
    for (int q = 0; q < 4; q++) {
        red[tr][tc*2 + 32*q]     = csm[2*q];
        red[tr][tc*2 + 32*q + 1] = csm[2*q+1];
    }
    __syncthreads();
    if (tid < 128) {
        float fsm = 0.f;
        #pragma unroll
        for (int t = 0; t < 16; t++) fsm += red[t][tid];
        float* o_ = out + ((size_t)(b*2 + 1)*L_ + tid) * OUTD;
        o_[36 + p] = fmx; o_[52 + p] = fsm / cnt1;
    }
}

// ---------------- cosine channel GEMM (32-row stripes, grid (4,B)=32 blocks, prefetched) ----
// Per thread: rows {2tr, 2tr+1}, col pairs 2tc+32q. A staged as {a,a} ull pairs.
__global__ __launch_bounds__(256) void k_gcos() {
    int b = blockIdx.y;
    int r0 = blockIdx.x * 32;
    const float* A  = g_c[0] + (size_t)(b*L_ + r0) * H_;
    const float* Bm = g_c[1] + (size_t)b * L_ * H_;
    __shared__ __align__(16) ull As2[16][32];       // pre-duplicated {a,a}
    __shared__ __align__(16) float Bs[16][128];
    int tid = threadIdx.x;
    int br = tid & 127, bk = (tid >> 7) << 3;       // B loader: row 0..127, koff {0,8}
    int ar = tid >> 2,  ak = (tid & 3) << 2;        // A loader (tid<128): row 0..31, koff {0,4,8,12}
    int tr = tid >> 4,  tc = tid & 15;              // compute

    ull acc[2][4];
    #pragma unroll
    for (int r = 0; r < 2; r++)
        #pragma unroll
        for (int q = 0; q < 4; q++) acc[r][q] = 0ull;

    unsigned int bs_b = (unsigned int)__cvta_generic_to_shared(&Bs[0][0]);
    unsigned int as_b = (unsigned int)__cvta_generic_to_shared(&As2[0][0]);

    float4 pb0, pb1, pa;
    pb0 = *(const float4*)(Bm + (size_t)br * H_ + bk);
    pb1 = *(const float4*)(Bm + (size_t)br * H_ + bk + 4);
    if (tid < 128) pa = *(const float4*)(A + (size_t)ar * H_ + ak);

    for (int c = 0; c < H_/16; c++) {
        Bs[bk+0][br]=pb0.x; Bs[bk+1][br]=pb0.y; Bs[bk+2][br]=pb0.z; Bs[bk+3][br]=pb0.w;
        Bs[bk+4][br]=pb1.x; Bs[bk+5][br]=pb1.y; Bs[bk+6][br]=pb1.z; Bs[bk+7][br]=pb1.w;
        if (tid < 128) {
            ull w;
            PACK2(w, pa.x); sts64(as_b + (unsigned int)((((ak+0)<<5) + ar) << 3), w);
            PACK2(w, pa.y); sts64(as_b + (unsigned int)((((ak+1)<<5) + ar) << 3), w);
            PACK2(w, pa.z); sts64(as_b + (unsigned int)((((ak+2)<<5) + ar) << 3), w);
            PACK2(w, pa.w); sts64(as_b + (unsigned int)((((ak+3)<<5) + ar) << 3), w);
        }
        __syncthreads();
        if (c + 1 < H_/16) {
            int k0 = (c + 1) * 16;
            pb0 = *(const float4*)(Bm + (size_t)br * H_ + k0 + bk);
            pb1 = *(const float4*)(Bm + (size_t)br * H_ + k0 + bk + 4);
            if (tid < 128) pa = *(const float4*)(A + (size_t)ar * H_ + k0 + ak);
        }
        #pragma unroll
        for (int k = 0; k < 16; k++) {
            ull aa0 = lds64(as_b + (unsigned int)((((k << 5) + 2*tr    )) << 3));
            ull aa1 = lds64(as_b + (unsigned int)((((k << 5) + 2*tr + 1)) << 3));
            unsigned int bb = bs_b + (unsigned int)((((k << 7) + (tc << 1))) << 2);
            ull b0 = lds64(bb);
            ull b1 = lds64(bb + 32*4);
            ull b2 = lds64(bb + 64*4);
            ull b3 = lds64(bb + 96*4);
            FMA2(acc[0][0], aa0, b0); FMA2(acc[0][1], aa0, b1);
            FMA2(acc[0][2], aa0, b2); FMA2(acc[0][3], aa0, b3);
            FMA2(acc[1][0], aa1, b0); FMA2(acc[1][1], aa1, b1);
            FMA2(acc[1][2], aa1, b2); FMA2(acc[1][3], aa1, b3);
        }
        __syncthreads();
    }

    float dl0 = fmaxf(g_n[0][b*L_ + r0 + 2*tr],     EPSF);
    float dl1 = fmaxf(g_n[0][b*L_ + r0 + 2*tr + 1], EPSF);
    #pragma unroll
    for (int q = 0; q < 4; q++) {
        int col = tc*2 + 32*q;
        float drx = fmaxf(g_n[1][b*L_ + col    ], EPSF);
        float dry = fmaxf(g_n[1][b*L_ + col + 1], EPSF);
        float l0, h0, l1, h1;
        UNPK2(l0, h0, acc[0][q]);
        UNPK2(l1, h1, acc[1][q]);
        float* d0 = g_Scos + ((size_t)(b*L_ + r0 + 2*tr    )) * L_ + col;
        float* d1 = g_Scos + ((size_t)(b*L_ + r0 + 2*tr + 1)) * L_ + col;
        *(float2*)d0 = make_float2(l0/(dl0*drx), h0/(dl0*dry));
        *(float2*)d1 = make_float2(l1/(dl1*drx), h1/(dl1*dry));
    }
}

// ---------------- attention sums/maxes + cos stats + fused softmax ----------------
#define ATT_BODY(CC, U) do {                                              \
    unsigned int _ub = cw_b + (unsigned int)((U) << 3);                   \
    _Pragma("unroll")                                                     \
    for (int tt = 0; tt < TT; tt++) {                                     \
        ull ww = lds64(_ub + (unsigned int)(tt * (L_*8)));                \
        ull pp; MUL2(pp, ww, (CC));                                       \
        FMA2(sm2[tt], ww, (CC));                                          \
        float pl, ph; UNPK2(pl, ph, pp);                                  \
        mxl[tt] = fmaxf(mxl[tt], pl);                                     \
        mxh[tt] = fmaxf(mxh[tt], ph);                                     \
    }                                                                     \
} while (0)

__global__ __launch_bounds__(ATT_THR) void k_att(
    const float* __restrict__ m1, const float* __restrict__ m2,
    float* __restrict__ out)
{
    int tb = blockIdx.x, b = blockIdx.y, s = blockIdx.z;
    int other = 1 - s;
    int lenO = g_len[other][b];           // always >= 64
    const float* C = g_c[other] + (size_t)b * L_ * H_;
    const float* Scos = g_Scos + (size_t)b * L_ * L_;
    const float* mkS = s ? m2 : m1;
    const float* mkO = s ? m1 : m2;       // mask over the reduced axis u
    __shared__ __align__(16) ull cw2[TT][L_];       // {w,w} duplicated pairs
    __shared__ float rmx[TT][ATT_W], rsm[TT][ATT_W];
    int tid = threadIdx.x;
    for (int idx = tid; idx < TT*L_; idx += ATT_THR) {
        int tt = idx >> 7, u = idx & (L_-1);
        int t = tb*TT + tt;
        float w = (s == 0) ? Scos[(size_t)t * L_ + u] : Scos[(size_t)u * L_ + t];
        ull ww; PACK2(ww, w);
        cw2[tt][u] = ww;
    }
    __syncthreads();

    int w = tid >> 5, lane = tid & 31;

    // cosine-channel masked max/mean over u  ->  out cols 0,1
    for (int tt = w; tt < TT; tt += ATT_W) {
        int t = tb*TT + tt;
        float mx = NEGINF, sm = 0.f;
        #pragma unroll
        for (int k4 = 0; k4 < 4; k4++) {
            int u = lane + (k4 << 5);
            float v = ((const float*)&cw2[tt][u])[0];
            if (mkO[b*L_ + u] != 0.f) { mx = fmaxf(mx, v); sm += v; }
        }
        #pragma unroll
        for (int o = 16; o; o >>= 1) {
            mx = fmaxf(mx, __shfl_xor_sync(0xffffffffu, mx, o));
            sm += __shfl_xor_sync(0xffffffffu, sm, o);
        }
        if (lane == 0) {
            float* o_ = out + ((size_t)(b*2 + s)*L_ + t) * OUTD;
            o_[0] = mx;
            o_[1] = sm / fmaxf((float)lenO, EPSF);
        }
    }

    unsigned int cw_b = (unsigned int)__cvta_generic_to_shared(&cw2[0][0]);
    ull sm2[TT];
    float mxl[TT], mxh[TT];
    #pragma unroll
    for (int tt = 0; tt < TT; tt++) { sm2[tt] = 0ull; mxl[tt] = NEGINF; mxh[tt] = NEGINF; }

    const float* Cp = C + 2*tid;
    // depth-4 prefetch ring (rows beyond lenO are zero-masked but valid; clamp to L_-1)
    ull c0 = ldg64(Cp);
    ull c1 = ldg64(Cp + H_);
    ull c2 = ldg64(Cp + 2*H_);
    ull c3 = ldg64(Cp + 3*H_);
    int u = 0;
    for (; u + 4 <= lenO; u += 4) {
        int n0 = u+4 < L_ ? u+4 : L_-1;
        int n1 = u+5 < L_ ? u+5 : L_-1;
        int n2 = u+6 < L_ ? u+6 : L_-1;
        int n3 = u+7 < L_ ? u+7 : L_-1;
        ATT_BODY(c0, u);     c0 = ldg64(Cp + (size_t)n0 * H_);
        ATT_BODY(c1, u+1);   c1 = ldg64(Cp + (size_t)n1 * H_);
        ATT_BODY(c2, u+2);   c2 = ldg64(Cp + (size_t)n2 * H_);
        ATT_BODY(c3, u+3);   c3 = ldg64(Cp + (size_t)n3 * H_);
    }
    if (u < lenO) { ATT_BODY(c0, u); u++; }
    if (u < lenO) { ATT_BODY(c1, u); u++; }
    if (u < lenO) { ATT_BODY(c2, u); u++; }

    // store maxes
    #pragma unroll
    for (int tt = 0; tt < TT; tt++) {
        int t = tb*TT + tt;
        size_t base = ((size_t)(b*L_ + t)) * H_;
        *(float2*)(&g_attM[s][base + 2*tid]) = make_float2(mxl[tt], mxh[tt]);
    }

    // fused softmax: stage per-warp partial maxes for all tokens, one sync
    float s0[TT], s1[TT];
    #pragma unroll
    for (int tt = 0; tt < TT; tt++) {
        UNPK2(s0[tt], s1[tt], sm2[tt]);
        float lm = fmaxf(s0[tt], s1[tt]);
        #pragma unroll
        for (int o = 16; o; o >>= 1) lm = fmaxf(lm, __shfl_xor_sync(0xffffffffu, lm, o));
        if (lane == 0) rmx[tt][w] = lm;
    }
    __syncthreads();
    float bm[TT];
    #pragma unroll
    for (int tt = 0; tt < TT; tt++) {
        float m = rmx[tt][0];
        #pragma unroll
        for (int i = 1; i < ATT_W; i++) m = fmaxf(m, rmx[tt][i]);
        bm[tt] = m;
    }
    float e0[TT], e1[TT];
    #pragma unroll
    for (int tt = 0; tt < TT; tt++) {
        e0[tt] = expf(s0[tt] - bm[tt]);
        e1[tt] = expf(s1[tt] - bm[tt]);
        float ls = e0[tt] + e1[tt];
        #pragma unroll
        for (int o = 16; o; o >>= 1) ls += __shfl_xor_sync(0xffffffffu, ls, o);
        if (lane == 0) rsm[tt][w] = ls;
    }
    __syncthreads();
    #pragma unroll
    for (int tt = 0; tt < TT; tt++) {
        int t = tb*TT + tt;
        size_t base = ((size_t)(b*L_ + t)) * H_;
        float m = mkS[b*L_ + t];
        if (m == 0.f) {
            *(float2*)(&g_attS[s][base + 2*tid]) = make_float2(1.f/(float)H_, 1.f/(float)H_);
            continue;
        }
        float bs = 0.f;
        #pragma unroll
        for (int i = 0; i < ATT_W; i++) bs += rsm[tt][i];
        float inv = 1.f / bs;
        *(float2*)(&g_attS[s][base + 2*tid]) = make_float2(e0[tt]*inv, e1[tt]*inv);
    }
}

// ---------------- per-token weighted cosines (packed f32x2) ----------------
__global__ __launch_bounds__(256) void k_final(
    const float* __restrict__ wff, const float* __restrict__ wfb,
    const float* __restrict__ watt, const float* __restrict__ wmatt,
    float* __restrict__ out)
{
    int t = blockIdx.x, b = blockIdx.y, s = blockIdx.z;
    int other = 1 - s;
    __shared__ __align__(16) float sa[H_];
    __shared__ __align__(16) float sv[4][H_];
    int tid = threadIdx.x;
    const float* a = g_c[s] + ((size_t)(b*L_ + t)) * H_;
    int lenO = g_len[other][b];
    int lp = lenO > 0 ? lenO - 1 : 0;
    const float* v_ff  = g_c[other] + ((size_t)(b*L_ + lp)) * H_;
    const float* v_bf  = g_c[other] + ((size_t)(b*L_)) * H_;
    const float* v_am  = g_attS[s] + ((size_t)(b*L_ + t)) * H_;
    const float* v_amx = g_attM[s] + ((size_t)(b*L_ + t)) * H_;
    for (int h = tid; h < H_; h += 256) {
        sa[h] = a[h];
        sv[0][h] = v_ff[h];
        sv[1][h] = v_bf[h];
        sv[2][h] = v_am[h];
        sv[3][h] = v_amx[h];
    }
    __syncthreads();

    unsigned int sa_b = (unsigned int)__cvta_generic_to_shared(sa);
    unsigned int sv_b = (unsigned int)__cvta_generic_to_shared(&sv[0][0]);
    int w = tid >> 5, lane = tid & 31;
    float* o_ = out + ((size_t)(b*2 + s)*L_ + t) * OUTD;
    for (int task = w; task < 68; task += 8) {
        int q = task / 17;
        int tt = task - q * 17;
        const float* W = (q == 0) ? wff : (q == 1) ? wfb : (q == 2) ? watt : wmatt;
        int base = (q == 0) ? 2 : (q == 1) ? 19 : (q == 2) ? 68 : 85;
        const float* Wr = W + tt * H_;
        unsigned int svq = sv_b + (unsigned int)(q * H_ * 4);
        ull sav = 0ull, saa = 0ull, svv = 0ull;
        if (tt < P_) {
            #pragma unroll
            for (int k = 0; k < 12; k++) {
                int h2 = (lane + (k << 5)) << 1;
                ull a2 = lds64(sa_b + (unsigned int)(h2 << 2));
                ull v2 = lds64(svq  + (unsigned int)(h2 << 2));
                ull w2 = ldg64(Wr + h2);
                MUL2(a2, a2, w2);
                MUL2(v2, v2, w2);
                FMA2(sav, a2, v2);
                FMA2(saa, a2, a2);
                FMA2(svv, v2, v2);
            }
        } else {
            #pragma unroll
            for (int k = 0; k < 12; k++) {
                int h2 = (lane + (k << 5)) << 1;
                ull a2 = lds64(sa_b + (unsigned int)(h2 << 2));
                ull v2 = lds64(svq  + (unsigned int)(h2 << 2));
                FMA2(sav, a2, v2);
                FMA2(saa, a2, a2);
                FMA2(svv, v2, v2);
            }
        }
        float lo, hi, fsav, fsaa, fsvv;
        UNPK2(lo, hi, sav); fsav = lo + hi;
        UNPK2(lo, hi, saa); fsaa = lo + hi;
        UNPK2(lo, hi, svv); fsvv = lo + hi;
        #pragma unroll
        for (int o = 16; o; o >>= 1) {
            fsav += __shfl_xor_sync(0xffffffffu, fsav, o);
            fsaa += __shfl_xor_sync(0xffffffffu, fsaa, o);
            fsvv += __shfl_xor_sync(0xffffffffu, fsvv, o);
        }
        if (lane == 0) {
            float na = fmaxf(sqrtf(fsaa), EPSF);
            float nv = fmaxf(sqrtf(fsvv), EPSF);
            int col = (tt == P_) ? base : (base + 1 + tt);
            o_[col] = fsav / (na * nv);
        }
    }
}

// ---------------- launch (fork weighted GEMM onto a side stream) ----------------
extern "C" void kernel_launch(void* const* d_in, const int* in_sizes, int n_in,
                              void* d_out, int out_size) {
    const float* c1    = (const float*)d_in[0];
    const float* m1    = (const float*)d_in[1];
    const float* c2    = (const float*)d_in[2];
    const float* m2    = (const float*)d_in[3];
    const float* wff   = (const float*)d_in[4];
    const float* wfb   = (const float*)d_in[5];
    const float* wmp   = (const float*)d_in[6];
    const float* watt  = (const float*)d_in[7];
    const float* wmatt = (const float*)d_in[8];
    float* out = (float*)d_out;
    (void)in_sizes; (void)n_in; (void)out_size;

    static cudaStream_t sB = nullptr;
    static cudaEvent_t evF = nullptr, evB = nullptr;
    if (!sB) {
        cudaStreamCreateWithFlags(&sB, cudaStreamNonBlocking);
        cudaEventCreateWithFlags(&evF, cudaEventDisableTiming);
        cudaEventCreateWithFlags(&evB, cudaEventDisableTiming);
    }

    k_len  <<<1, 64>>>(m1, m2);
    k_prep <<<dim3(L_, B_, 2), 256>>>(c1, m1, c2, m2, wmp);

    // fork: weighted GEMM on side stream, cosine chain on main stream
    cudaEventRecord(evF, 0);
    cudaStreamWaitEvent(sB, evF, 0);
    k_gemm <<<dim3(P_, B_), 256, 0, sB>>>(wmp, m1, m2, out);
    cudaEventRecord(evB, sB);

    k_gcos  <<<dim3(4, B_), 256>>>();
    k_att   <<<dim3(L_/TT, B_, 2), ATT_THR>>>(m1, m2, out);
    k_final <<<dim3(L_, B_, 2), 256>>>(wff, wfb, watt, wmatt, out);

    // join
    cudaStreamWaitEvent(0, evB, 0);
}